// round 17
// baseline (speedup 1.0000x reference)
#include <cuda_runtime.h>
#include <cuda_bf16.h>
#include <cstdint>

#define BB 8
#define NN 4096
#define MM 4096
#define DD 128

// ===================== device scratch (no allocations allowed) =====================
__device__ __nv_bfloat16 g_d0h[(size_t)BB * NN * DD];
__device__ __nv_bfloat16 g_d0l[(size_t)BB * NN * DD];
__device__ __nv_bfloat16 g_d1h[(size_t)BB * MM * DD];
__device__ __nv_bfloat16 g_d1l[(size_t)BB * MM * DD];
__device__ int g_m0raw[BB * NN];
__device__ int g_m1raw[BB * MM];

// ===================== normalize + bf16 hi/lo split =====================
__global__ void norm_kernel(const float* __restrict__ in,
                            __nv_bfloat16* __restrict__ hi,
                            __nv_bfloat16* __restrict__ lo, int rows) {
    int row = blockIdx.x * (blockDim.x >> 5) + (threadIdx.x >> 5);
    if (row >= rows) return;
    int lane = threadIdx.x & 31;
    float4 v = ((const float4*)(in + (size_t)row * DD))[lane];
    float ss = v.x * v.x + v.y * v.y + v.z * v.z + v.w * v.w;
    #pragma unroll
    for (int o = 16; o > 0; o >>= 1) ss += __shfl_xor_sync(0xffffffffu, ss, o);
    float inv = 1.0f / fmaxf(sqrtf(ss), 1e-12f);
    float n0 = v.x * inv, n1 = v.y * inv, n2 = v.z * inv, n3 = v.w * inv;
    __nv_bfloat16 h0 = __float2bfloat16(n0), h1 = __float2bfloat16(n1);
    __nv_bfloat16 h2 = __float2bfloat16(n2), h3 = __float2bfloat16(n3);
    __nv_bfloat16 l0 = __float2bfloat16(n0 - __bfloat162float(h0));
    __nv_bfloat16 l1 = __float2bfloat16(n1 - __bfloat162float(h1));
    __nv_bfloat16 l2 = __float2bfloat16(n2 - __bfloat162float(h2));
    __nv_bfloat16 l3 = __float2bfloat16(n3 - __bfloat162float(h3));
    __nv_bfloat162* ph = (__nv_bfloat162*)(hi + (size_t)row * DD + lane * 4);
    __nv_bfloat162* pl = (__nv_bfloat162*)(lo + (size_t)row * DD + lane * 4);
    ph[0] = __nv_bfloat162(h0, h1); ph[1] = __nv_bfloat162(h2, h3);
    pl[0] = __nv_bfloat162(l0, l1); pl[1] = __nv_bfloat162(l2, l3);
}

// ===================== top-2 helpers (tie: lower index wins) =====================
__device__ __forceinline__ bool better(float va, int ia, float vb, int ib) {
    return (va > vb) || (va == vb && ia < ib);
}
__device__ __forceinline__ void t2_update(float v, int idx, float& v0, int& i0, float& v1, int& i1) {
    if (better(v, idx, v0, i0)) { v1 = v0; i1 = i0; v0 = v; i0 = idx; }
    else if (better(v, idx, v1, i1)) { v1 = v; i1 = idx; }
}
// merge a remote sorted top-2 (from shfl_xor o) into local state
__device__ __forceinline__ void t2_merge_x(float& v0, int& i0, float& v1, int& i1, int o) {
    float w0 = __shfl_xor_sync(0xffffffffu, v0, o);
    int   j0 = __shfl_xor_sync(0xffffffffu, i0, o);
    float w1 = __shfl_xor_sync(0xffffffffu, v1, o);
    int   j1 = __shfl_xor_sync(0xffffffffu, i1, o);
    if (better(w0, j0, v0, i0)) {
        if (better(v0, i0, w1, j1)) { v1 = v0; i1 = i0; }
        else                        { v1 = w1; i1 = j1; }
        v0 = w0; i0 = j0;
    } else if (better(w0, j0, v1, i1)) { v1 = w0; i1 = j0; }
}
__device__ __forceinline__ int ratio_test(float v0, int i0, float v1) {
    float d0 = 2.0f * (1.0f - v0);
    float d1 = 2.0f * (1.0f - v1);
    bool ok = (d0 <= 0.64f * d1) && (d0 <= 0.49f);
    return ok ? i0 : -1;
}

// ===================== misc asm helpers =====================
__device__ __forceinline__ uint32_t smem_u32(const void* p) {
    uint32_t a;
    asm("{ .reg .u64 t; cvta.to.shared.u64 t, %1; cvt.u32.u64 %0, t; }" : "=r"(a) : "l"(p));
    return a;
}
__device__ __forceinline__ void cp16(uint32_t saddr, const void* g) {
    asm volatile("cp.async.cg.shared.global [%0], [%1], 16;" :: "r"(saddr), "l"(g));
}
#define LDSM_X4(r, a) \
    asm volatile("ldmatrix.sync.aligned.m8n8.x4.shared.b16 {%0,%1,%2,%3}, [%4];" \
        : "=r"((r)[0]), "=r"((r)[1]), "=r"((r)[2]), "=r"((r)[3]) : "r"(a))
#define MMA16816(acc, a, b0_, b1_) \
    asm volatile("mma.sync.aligned.m16n8k16.row.col.f32.bf16.bf16.f32 " \
        "{%0,%1,%2,%3},{%4,%5,%6,%7},{%8,%9},{%0,%1,%2,%3};" \
        : "+f"((acc)[0]), "+f"((acc)[1]), "+f"((acc)[2]), "+f"((acc)[3]) \
        : "r"((a)[0]), "r"((a)[1]), "r"((a)[2]), "r"((a)[3]), "r"(b0_), "r"(b1_))

// ===================== pipelined warp-MMA GEMM + fused row top-2 =====================
// CTA: 64-row A panel resident, streams 32 B tiles with cp.async double buffering.
// 256 threads = 8 warps (2x4), warp tile 32x32, 3-pass hi/lo bf16.
// Each thread keeps a running top-2 over M for its 4 rows; final merge -> g_m0raw.
#define SMA_H 0
#define SMA_L 16384
#define SMB_BASE 32768
#define SMB_SZ 65536
#define SM_TOTAL_G (SMB_BASE + 2 * SMB_SZ)   // 160 KB

__global__ void __launch_bounds__(256, 1)
gemm_pipe_kernel(float* __restrict__ sim) {
    extern __shared__ char smem[];
    const uint32_t sb = smem_u32(smem);

    const int x = blockIdx.x;
    const int b = x >> 6, np = x & 63;
    const int n0 = np << 6;
    const int tid = threadIdx.x;
    const int wid = tid >> 5, lane = tid & 31;
    const int wm = wid >> 2, wn = wid & 3;

    const char* a_h = (const char*)(g_d0h + ((size_t)b * NN + n0) * DD);
    const char* a_l = (const char*)(g_d0l + ((size_t)b * NN + n0) * DD);
    const char* b_h = (const char*)(g_d1h + (size_t)b * MM * DD);
    const char* b_l = (const char*)(g_d1l + (size_t)b * MM * DD);

    #pragma unroll
    for (int i = tid; i < 1024; i += 256) {
        int row = i >> 4, ch = i & 15;
        uint32_t soff = (uint32_t)(row * 256 + ((ch ^ (row & 7)) << 4));
        cp16(sb + SMA_H + soff, a_h + (size_t)i * 16);
        cp16(sb + SMA_L + soff, a_l + (size_t)i * 16);
    }
    #pragma unroll
    for (int i = tid; i < 2048; i += 256) {
        int row = i >> 4, ch = i & 15;
        uint32_t soff = (uint32_t)(row * 256 + ((ch ^ (row & 7)) << 4));
        cp16(sb + SMB_BASE + soff, b_h + (size_t)i * 16);
        cp16(sb + SMB_BASE + 32768 + soff, b_l + (size_t)i * 16);
    }
    asm volatile("cp.async.commit_group;" ::: "memory");

    const int a_row = wm * 32 + (lane & 15);
    const int a_cof = (lane >> 4) & 1;
    const int b_row = wn * 32 + (lane & 7) + ((lane >> 4) << 3);
    const int b_cof = (lane >> 3) & 1;
    const int g = lane >> 2, c2 = (lane & 3) * 2;

    // running row top-2: 4 rows/thread -> idx s = tm*2 + h, row = wm*32+tm*16+h*8+g
    float rv0[4] = {-2.f, -2.f, -2.f, -2.f}, rv1[4] = {-2.f, -2.f, -2.f, -2.f};
    int   ri0[4] = {-1, -1, -1, -1},          ri1[4] = {-1, -1, -1, -1};

    for (int mt = 0; mt < 32; mt++) {
        if (mt < 31) {
            uint32_t nbuf = sb + SMB_BASE + (uint32_t)((mt + 1) & 1) * SMB_SZ;
            const char* nbh = b_h + (size_t)(mt + 1) * 128 * 256;
            const char* nbl = b_l + (size_t)(mt + 1) * 128 * 256;
            #pragma unroll
            for (int i = tid; i < 2048; i += 256) {
                int row = i >> 4, ch = i & 15;
                uint32_t soff = (uint32_t)(row * 256 + ((ch ^ (row & 7)) << 4));
                cp16(nbuf + soff, nbh + (size_t)i * 16);
                cp16(nbuf + 32768 + soff, nbl + (size_t)i * 16);
            }
            asm volatile("cp.async.commit_group;" ::: "memory");
            asm volatile("cp.async.wait_group 1;" ::: "memory");
        } else {
            asm volatile("cp.async.wait_group 0;" ::: "memory");
        }
        __syncthreads();

        const uint32_t cbh = sb + SMB_BASE + (uint32_t)(mt & 1) * SMB_SZ;
        const uint32_t cbl = cbh + 32768;

        float acc[2][4][4];
        #pragma unroll
        for (int tm = 0; tm < 2; tm++)
            #pragma unroll
            for (int j = 0; j < 4; j++)
                #pragma unroll
                for (int q = 0; q < 4; q++) acc[tm][j][q] = 0.f;

        #pragma unroll
        for (int ks = 0; ks < 8; ks++) {
            uint32_t ah[2][4], al[2][4], bh[2][4], bl[2][4];
            #pragma unroll
            for (int tm = 0; tm < 2; tm++) {
                int row = a_row + tm * 16;
                uint32_t addr = (uint32_t)(row * 256 + (((2 * ks + a_cof) ^ (row & 7)) << 4));
                LDSM_X4(ah[tm], sb + SMA_H + addr);
                LDSM_X4(al[tm], sb + SMA_L + addr);
            }
            #pragma unroll
            for (int tb = 0; tb < 2; tb++) {
                int row = b_row + tb * 16;
                uint32_t addr = (uint32_t)(row * 256 + (((2 * ks + b_cof) ^ (row & 7)) << 4));
                LDSM_X4(bh[tb], cbh + addr);
                LDSM_X4(bl[tb], cbl + addr);
            }
            #pragma unroll
            for (int tm = 0; tm < 2; tm++)
                #pragma unroll
                for (int j = 0; j < 4; j++) {
                    int tb = j >> 1, s = (j & 1) * 2;
                    MMA16816(acc[tm][j], ah[tm], bh[tb][s], bh[tb][s + 1]);  // hi*hi
                    MMA16816(acc[tm][j], ah[tm], bl[tb][s], bl[tb][s + 1]);  // hi*lo
                    MMA16816(acc[tm][j], al[tm], bh[tb][s], bh[tb][s + 1]);  // lo*hi
                }
        }

        // write sim slice + fused row top-2 update
        #pragma unroll
        for (int tm = 0; tm < 2; tm++) {
            #pragma unroll
            for (int j = 0; j < 4; j++) {
                size_t row0 = (size_t)b * NN + n0 + wm * 32 + tm * 16 + g;
                int col = mt * 128 + wn * 32 + j * 8 + c2;
                *(float2*)(sim + row0 * MM + col)       = make_float2(acc[tm][j][0], acc[tm][j][1]);
                *(float2*)(sim + (row0 + 8) * MM + col) = make_float2(acc[tm][j][2], acc[tm][j][3]);
                t2_update(acc[tm][j][0], col,     rv0[tm * 2],     ri0[tm * 2],     rv1[tm * 2],     ri1[tm * 2]);
                t2_update(acc[tm][j][1], col + 1, rv0[tm * 2],     ri0[tm * 2],     rv1[tm * 2],     ri1[tm * 2]);
                t2_update(acc[tm][j][2], col,     rv0[tm * 2 + 1], ri0[tm * 2 + 1], rv1[tm * 2 + 1], ri1[tm * 2 + 1]);
                t2_update(acc[tm][j][3], col + 1, rv0[tm * 2 + 1], ri0[tm * 2 + 1], rv1[tm * 2 + 1], ri1[tm * 2 + 1]);
            }
        }
        __syncthreads();
    }

    // ---- final row-top2 merge: lanes with same g (lane&3 varies) -> smem across wn -> serial
    #pragma unroll
    for (int s = 0; s < 4; s++) {
        t2_merge_x(rv0[s], ri0[s], rv1[s], ri1[s], 1);
        t2_merge_x(rv0[s], ri0[s], rv1[s], ri1[s], 2);
    }
    float4* Sm = (float4*)smem;   // 64 rows x 4 wn = 4KB (A/B buffers dead)
    if ((lane & 3) == 0) {
        #pragma unroll
        for (int s = 0; s < 4; s++) {
            int rloc = wm * 32 + (s >> 1) * 16 + (s & 1) * 8 + g;
            Sm[rloc * 4 + wn] = make_float4(rv0[s], __int_as_float(ri0[s]),
                                            rv1[s], __int_as_float(ri1[s]));
        }
    }
    __syncthreads();
    if (tid < 64) {
        float v0 = -2.f, v1 = -2.f; int i0 = -1, i1 = -1;
        #pragma unroll
        for (int w = 0; w < 4; w++) {
            float4 p = Sm[tid * 4 + w];
            float w0 = p.x, w1 = p.z;
            int j0 = __float_as_int(p.y), j1 = __float_as_int(p.w);
            if (better(w0, j0, v0, i0)) {
                if (better(v0, i0, w1, j1)) { v1 = v0; i1 = i0; }
                else                        { v1 = w1; i1 = j1; }
                v0 = w0; i0 = j0;
            } else if (better(w0, j0, v1, i1)) { v1 = w0; i1 = j0; }
        }
        g_m0raw[b * NN + n0 + tid] = ratio_test(v0, i0, v1);
    }
}

// ===================== column top-2: thread per column, coalesced =====================
__global__ void coltop2_kernel(const float* __restrict__ sim) {
    int b = blockIdx.y;
    int m = blockIdx.x * blockDim.x + threadIdx.x;
    const float* p = sim + (size_t)b * NN * MM + m;

    float v0 = -2.f, v1 = -2.f; int i0 = -1, i1 = -1;
    #pragma unroll 8
    for (int n = 0; n < NN; n++) {
        float v = __ldg(p + (size_t)n * MM);
        if (v > v0)      { v1 = v0; i1 = i0; v0 = v; i0 = n; }
        else if (v > v1) { v1 = v; i1 = n; }
    }
    g_m1raw[b * MM + m] = ratio_test(v0, i0, v1);
}

// ---------------- mutual check + small outputs ----------------
__global__ void mutual_kernel(float* __restrict__ out) {
    int i = blockIdx.x * blockDim.x + threadIdx.x;
    if (i >= BB * NN) return;
    int b = i >> 12, n = i & 4095;
    int a = g_m0raw[i];
    int r0 = (a > -1 && g_m1raw[(b << 12) + a] == n) ? a : -1;
    int c = g_m1raw[i];
    int r1 = (c > -1 && g_m0raw[(b << 12) + c] == n) ? c : -1;
    const int BN = BB * NN;
    out[i]          = (float)r0;
    out[BN + i]     = (float)r1;
    out[2 * BN + i] = (r0 > -1) ? 1.0f : 0.0f;
    out[3 * BN + i] = (r1 > -1) ? 1.0f : 0.0f;
}

// ===================== launch =====================
extern "C" void kernel_launch(void* const* d_in, const int* in_sizes, int n_in,
                              void* d_out, int out_size) {
    const float* desc0 = (const float*)d_in[0];
    const float* desc1 = (const float*)d_in[1];
    float* out = (float*)d_out;
    float* sim = out + 4 * BB * NN;

    __nv_bfloat16 *d0h, *d0l, *d1h, *d1l;
    cudaGetSymbolAddress((void**)&d0h, g_d0h);
    cudaGetSymbolAddress((void**)&d0l, g_d0l);
    cudaGetSymbolAddress((void**)&d1h, g_d1h);
    cudaGetSymbolAddress((void**)&d1l, g_d1l);

    cudaFuncSetAttribute(gemm_pipe_kernel, cudaFuncAttributeMaxDynamicSharedMemorySize, SM_TOTAL_G);

    norm_kernel<<<(BB * NN) / 8, 256>>>(desc0, d0h, d0l, BB * NN);
    norm_kernel<<<(BB * MM) / 8, 256>>>(desc1, d1h, d1l, BB * MM);

    gemm_pipe_kernel<<<BB * 64, 256, SM_TOTAL_G>>>(sim);

    dim3 cgrid(MM / 256, BB);
    coltop2_kernel<<<cgrid, 256>>>(sim);

    mutual_kernel<<<(BB * NN + 255) / 256, 256>>>(out);
}